// round 7
// baseline (speedup 1.0000x reference)
#include <cuda_runtime.h>

// Problem constants (fixed): B=4, T=4096, d=64, q=256, Ctraj=32, nA=4, L=1024, C=2.
// Aset t,j indices are in [0,256).
#define CAP 64   // bucket capacity per (b,j): Binom(4096,1/256) mean 16, 64 = ~12 sigma

// Scratch (__device__ globals; no allocations allowed)
__device__ float        g_x2[4*256];        // [b][t], t<256 only
__device__ float        g_S[1024];          // [b][a][c][{sum e, sum phi*e}]
__device__ int          g_bk[4*256*CAP];    // buckets: packed (a<<16)|t
__device__ int          g_cnt[4*256];       // bucket counts
__device__ unsigned int g_done;             // completion counter (reset each run)

// ---------------------------------------------------------------------------
// prep (9 blocks):
//  blocks 0..3 : bin Aset entries of batch b by j (smem counters, block-local)
//  blocks 4..7 : x2[b][t] = ||traj[b][t]||^2 for t<256
//  block  8    : zero g_S, g_done
// ---------------------------------------------------------------------------
__global__ void __launch_bounds__(256) prep_kernel(const float* __restrict__ traj,
                                                   const int2* __restrict__ Aset) {
    const int bid = blockIdx.x, tid = threadIdx.x;
    if (bid < 4) {
        __shared__ int cnt[256];
        cnt[tid] = 0;
        __syncthreads();
        const int2* A2 = Aset + bid*4096;
        #pragma unroll
        for (int r = 0; r < 16; r++) {
            int e = r*256 + tid;
            int2 ta = A2[e];                       // (t, j)
            int pos = atomicAdd(&cnt[ta.y], 1);
            if (pos < CAP)
                g_bk[(bid*256 + ta.y)*CAP + pos] = ta.x | ((e >> 10) << 16); // a = e/1024
        }
        __syncthreads();
        g_cnt[bid*256 + tid] = min(cnt[tid], CAP);
    } else if (bid < 8) {
        int b = bid - 4;
        const float4* src = (const float4*)(traj + (size_t)(b*4096 + tid)*64);
        float s = 0.f;
        #pragma unroll
        for (int i = 0; i < 16; i++) {
            float4 v = src[i];
            s += v.x*v.x + v.y*v.y + v.z*v.z + v.w*v.w;
        }
        g_x2[b*256 + tid] = s;
    } else {
        for (int i = tid; i < 1024; i += 256) g_S[i] = 0.f;
        if (tid == 0) g_done = 0;
    }
}

// ---------------------------------------------------------------------------
// main (256 blocks, one per j; 128 threads = 4 warps):
//  - stage Y[:, :, j] (8 KB) into smem as float4 [i][c]
//  - per b: each warp processes its bucket entries in groups of 4
//    (register-blocked: one Y LDS.128 feeds 4 entries)
//  - per-warp smem partials -> block reduce -> global atomics
//  - last block computes the final linear+SELU (fused, no 3rd kernel)
// ---------------------------------------------------------------------------
__global__ void __launch_bounds__(128) main_kernel(const float* __restrict__ traj,
                                                   const float* __restrict__ Y,
                                                   const float* __restrict__ W,
                                                   const float* __restrict__ bias,
                                                   float* __restrict__ out) {
    const int j = blockIdx.x;
    const int tid = threadIdx.x, lane = tid & 31, w = tid >> 5;

    __shared__ float  Ysf[2048];        // [i][c] as float4: Ysf[i*128 + c*4 + k]
    __shared__ float4 xwv[4][4][16];    // [warp][entry][i]
    __shared__ float  Sw[4][1024];      // per-warp partials, layout [b][a][c][2]
    __shared__ unsigned int s_win;

    // Stage Y slice for this j (scattered 4B reads, L2-resident after first touch)
    #pragma unroll
    for (int r = 0; r < 16; r++) {
        int flat = r*128 + tid;
        int c = flat & 31, rest = flat >> 5;
        int i = rest & 15, k = rest >> 4;
        Ysf[i*128 + c*4 + k] = Y[c*16384 + (4*i + k)*256 + j];
    }
    __syncthreads();

    const float4* Ysv = (const float4*)Ysf;

    // y2 for this lane's c (computed per warp from smem; negligible)
    float y2c = 0.f;
    #pragma unroll
    for (int i = 0; i < 16; i++) {
        float4 y4 = Ysv[i*32 + lane];
        y2c += y4.x*y4.x + y4.y*y4.y + y4.z*y4.z + y4.w*y4.w;
    }

    const float4* traj4 = (const float4*)traj;

    #pragma unroll
    for (int b = 0; b < 4; b++) {
        float s1[4] = {0.f,0.f,0.f,0.f}, s2[4] = {0.f,0.f,0.f,0.f};
        const int nb = g_cnt[b*256 + j];
        const int* bk = g_bk + (b*256 + j)*CAP;

        for (int g0 = w*4; g0 < nb; g0 += 16) {
            const int cnt = min(4, nb - g0);
            int rec[4];
            #pragma unroll
            for (int e = 0; e < 4; e++)
                rec[e] = (e < cnt) ? bk[g0 + e] : 0;   // broadcast load

            // Stage up to 4 traj rows: 2 float4 per lane
            #pragma unroll
            for (int rr = 0; rr < 2; rr++) {
                int flat = rr*32 + lane;
                int e = flat >> 4, i = flat & 15;
                float4 v = make_float4(0.f,0.f,0.f,0.f);
                if (e < cnt) {
                    int t = rec[e] & 0xffff;
                    v = traj4[(size_t)(b*4096 + t)*16 + i];
                }
                xwv[w][e][i] = v;
            }
            __syncwarp();

            float acc[4] = {0.f,0.f,0.f,0.f};
            #pragma unroll
            for (int i = 0; i < 16; i++) {
                float4 y4 = Ysv[i*32 + lane];       // one Y load serves 4 entries
                #pragma unroll
                for (int e = 0; e < 4; e++) {
                    float4 x4 = xwv[w][e][i];       // broadcast
                    acc[e] += x4.x*y4.x + x4.y*y4.y + x4.z*y4.z + x4.w*y4.w;
                }
            }

            #pragma unroll
            for (int e = 0; e < 4; e++) {
                if (e < cnt) {
                    int t = rec[e] & 0xffff, a = rec[e] >> 16;
                    float D  = g_x2[b*256 + t] + y2c - 2.f*acc[e];
                    float ph = __expf(-D * (1.f/256.f));
                    float ex = __expf(-10.f * ph);
                    float pe = ph * ex;
                    #pragma unroll
                    for (int aa = 0; aa < 4; aa++)
                        if (a == aa) { s1[aa] += ex; s2[aa] += pe; }
                }
            }
            __syncwarp();   // everyone done reading xwv before next overwrite
        }

        // Per-warp flush (plain stores; each warp owns its Sw slice)
        #pragma unroll
        for (int aa = 0; aa < 4; aa++) {
            Sw[w][b*256 + aa*64 + lane*2 + 0] = s1[aa];
            Sw[w][b*256 + aa*64 + lane*2 + 1] = s2[aa];
        }
    }
    __syncthreads();

    // Cross-warp reduce + global accumulate
    for (int idx = tid; idx < 1024; idx += 128) {
        float v = Sw[0][idx] + Sw[1][idx] + Sw[2][idx] + Sw[3][idx];
        atomicAdd(&g_S[idx], v);
    }
    __threadfence();
    __syncthreads();
    if (tid == 0) s_win = atomicAdd(&g_done, 1u);
    __syncthreads();

    // Last block to finish computes the output (fused final stage)
    if (s_win == gridDim.x - 1) {
        if (tid == 0) g_done = 0;                 // reset for next graph replay
        int b = tid >> 5, c = tid & 31;
        float odds = 0.f;
        #pragma unroll
        for (int a = 0; a < 4; a++) {
            float v1 = __ldcg(&g_S[b*256 + a*64 + c*2 + 0]);
            float v2 = __ldcg(&g_S[b*256 + a*64 + c*2 + 1]);
            odds += v2 / (1024.f * v1);
        }
        float p0 = odds * W[c];
        float p1 = odds * W[32 + c];
        #pragma unroll
        for (int off = 16; off; off >>= 1) {
            p0 += __shfl_xor_sync(0xffffffffu, p0, off);
            p1 += __shfl_xor_sync(0xffffffffu, p1, off);
        }
        if (c == 0) {
            const float sc = 1.0507009873554805f, al = 1.6732632423543772f;
            float x0 = p0 + bias[0];
            float x1 = p1 + bias[1];
            out[b*2 + 0] = (x0 > 0.f) ? sc*x0 : sc*al*expm1f(x0);
            out[b*2 + 1] = (x1 > 0.f) ? sc*x1 : sc*al*expm1f(x1);
        }
    }
}

// ---------------------------------------------------------------------------
extern "C" void kernel_launch(void* const* d_in, const int* in_sizes, int n_in,
                              void* d_out, int out_size) {
    const float* traj = (const float*)d_in[0];   // (4,4096,64)
    const int2*  Aset = (const int2*) d_in[1];   // (4,4,1024,2)
    const float* Y    = (const float*)d_in[2];   // (32,64,256)
    const float* W    = (const float*)d_in[3];   // (2,32)
    const float* bias = (const float*)d_in[4];   // (2,)
    float* out = (float*)d_out;                  // (4,2)

    prep_kernel<<<9, 256>>>(traj, Aset);
    main_kernel<<<256, 128>>>(traj, Y, W, bias, out);
}